// round 1
// baseline (speedup 1.0000x reference)
#include <cuda_runtime.h>
#include <math.h>
#include <stdint.h>

#define NTOK 4096
#define CDIM 1024
#define HDIM 4096
#define NEXP 8

// Routing scratch (allocation-free: static __device__ globals).
__device__ int   g_count[NEXP];
__device__ int   g_bucket[NEXP][NTOK];
__device__ float g_wt[NEXP][NTOK];
// Hidden activations: per-expert capacity NTOK rows of HDIM (worst case).
__device__ float g_h[(size_t)NEXP * NTOK * HDIM];

// ---------------------------------------------------------------------------
// Zero output + counters
// ---------------------------------------------------------------------------
__global__ void zero_kernel(float* __restrict__ out) {
    size_t i = (size_t)blockIdx.x * blockDim.x + threadIdx.x;
    if (i < (size_t)NTOK * CDIM) out[i] = 0.0f;
    if (i < NEXP) g_count[i] = 0;
}

// ---------------------------------------------------------------------------
// Gating: one warp per token. logits = x[n] @ gate_w, softmax-top2-renorm.
// ---------------------------------------------------------------------------
__global__ void gate_kernel(const float* __restrict__ x,
                            const float* __restrict__ gw) {
    int gtid = blockIdx.x * blockDim.x + threadIdx.x;
    int tok  = gtid >> 5;
    int lane = threadIdx.x & 31;
    if (tok >= NTOK) return;

    float p[NEXP];
#pragma unroll
    for (int e = 0; e < NEXP; e++) p[e] = 0.0f;

    const float* xr = x + (size_t)tok * CDIM;
    for (int k = lane; k < CDIM; k += 32) {
        float xv = xr[k];
        const float* gr = gw + (size_t)k * NEXP;
#pragma unroll
        for (int e = 0; e < NEXP; e++) p[e] += xv * gr[e];
    }
#pragma unroll
    for (int off = 16; off > 0; off >>= 1) {
#pragma unroll
        for (int e = 0; e < NEXP; e++)
            p[e] += __shfl_xor_sync(0xFFFFFFFFu, p[e], off);
    }
    if (lane == 0) {
        int e0 = 0;
#pragma unroll
        for (int e = 1; e < NEXP; e++) if (p[e] > p[e0]) e0 = e;
        int e1 = -1;
#pragma unroll
        for (int e = 0; e < NEXP; e++)
            if (e != e0 && (e1 < 0 || p[e] > p[e1])) e1 = e;
        // renormalized top-2 softmax weights (temperature = 1)
        float w0 = 1.0f / (1.0f + expf(p[e1] - p[e0]));
        float w1 = 1.0f - w0;
        int s0 = atomicAdd(&g_count[e0], 1);
        g_bucket[e0][s0] = tok; g_wt[e0][s0] = w0;
        int s1 = atomicAdd(&g_count[e1], 1);
        g_bucket[e1][s1] = tok; g_wt[e1][s1] = w1;
    }
}

// ---------------------------------------------------------------------------
// GEMM1: H[m, j] = gelu( X[bucket[m], :] @ W1[e][:, j] + b1[e][j] )
// 128x128 block tile, BK=8, 256 threads, 8x8 per thread.
// ---------------------------------------------------------------------------
__global__ __launch_bounds__(256) void gemm1_kernel(
    const float* __restrict__ x, const float* __restrict__ w1,
    const float* __restrict__ b1) {
    int e = blockIdx.z;
    int T = g_count[e];
    int mt = blockIdx.y, jt = blockIdx.x;
    if (mt * 128 >= T) return;

    __shared__ __align__(16) float As[8][128];
    __shared__ __align__(16) float Bs[8][128];

    int tid = threadIdx.x;
    int tx = tid & 15, ty = tid >> 4;

    int arow = tid >> 1;
    int akq  = (tid & 1) * 4;
    int am   = mt * 128 + arow;
    int tok  = (am < T) ? g_bucket[e][am] : -1;
    const float* aptr = (tok >= 0) ? (x + (size_t)tok * CDIM) : nullptr;

    int bkr = tid >> 5;
    int bjq = (tid & 31) * 4;
    const float* bptr = w1 + (size_t)e * CDIM * HDIM + (size_t)bkr * HDIM
                        + (size_t)jt * 128 + bjq;

    float acc[8][8];
#pragma unroll
    for (int i = 0; i < 8; i++)
#pragma unroll
        for (int j = 0; j < 8; j++) acc[i][j] = 0.0f;

    for (int kt = 0; kt < CDIM; kt += 8) {
        float4 av = make_float4(0.f, 0.f, 0.f, 0.f);
        if (aptr) av = *reinterpret_cast<const float4*>(aptr + kt + akq);
        As[akq + 0][arow] = av.x; As[akq + 1][arow] = av.y;
        As[akq + 2][arow] = av.z; As[akq + 3][arow] = av.w;

        float4 bv = *reinterpret_cast<const float4*>(bptr + (size_t)kt * HDIM);
        *reinterpret_cast<float4*>(&Bs[bkr][bjq]) = bv;
        __syncthreads();

#pragma unroll
        for (int k = 0; k < 8; k++) {
            float a[8], b[8];
#pragma unroll
            for (int i = 0; i < 8; i++) a[i] = As[k][ty * 8 + i];
#pragma unroll
            for (int j = 0; j < 8; j++) b[j] = Bs[k][tx * 8 + j];
#pragma unroll
            for (int i = 0; i < 8; i++)
#pragma unroll
                for (int j = 0; j < 8; j++) acc[i][j] += a[i] * b[j];
        }
        __syncthreads();
    }

#pragma unroll
    for (int i = 0; i < 8; i++) {
        int m = mt * 128 + ty * 8 + i;
        if (m >= T) continue;
        size_t hbase = ((size_t)e * NTOK + m) * HDIM;
#pragma unroll
        for (int j = 0; j < 8; j++) {
            int jg = jt * 128 + tx * 8 + j;
            float v = acc[i][j] + b1[e * HDIM + jg];
            // exact GELU
            float g = 0.5f * v * (1.0f + erff(v * 0.70710678118654752f));
            g_h[hbase + jg] = g;
        }
    }
}

// ---------------------------------------------------------------------------
// GEMM2: out[tok, i] += wt[m] * ( H[m, :] @ W2[e][:, i] + b2[e][i] )
// ---------------------------------------------------------------------------
__global__ __launch_bounds__(256) void gemm2_kernel(
    const float* __restrict__ w2, const float* __restrict__ b2,
    float* __restrict__ out) {
    int e = blockIdx.z;
    int T = g_count[e];
    int mt = blockIdx.y, jt = blockIdx.x;
    if (mt * 128 >= T) return;

    __shared__ __align__(16) float As[8][128];
    __shared__ __align__(16) float Bs[8][128];

    int tid = threadIdx.x;
    int tx = tid & 15, ty = tid >> 4;

    int arow = tid >> 1;
    int akq  = (tid & 1) * 4;
    int am   = mt * 128 + arow;
    const float* aptr = (am < T) ? &g_h[((size_t)e * NTOK + am) * HDIM] : nullptr;

    int bkr = tid >> 5;
    int bjq = (tid & 31) * 4;
    const float* bptr = w2 + (size_t)e * HDIM * CDIM + (size_t)bkr * CDIM
                        + (size_t)jt * 128 + bjq;

    float acc[8][8];
#pragma unroll
    for (int i = 0; i < 8; i++)
#pragma unroll
        for (int j = 0; j < 8; j++) acc[i][j] = 0.0f;

    for (int kt = 0; kt < HDIM; kt += 8) {
        float4 av = make_float4(0.f, 0.f, 0.f, 0.f);
        if (aptr) av = *reinterpret_cast<const float4*>(aptr + kt + akq);
        As[akq + 0][arow] = av.x; As[akq + 1][arow] = av.y;
        As[akq + 2][arow] = av.z; As[akq + 3][arow] = av.w;

        float4 bv = *reinterpret_cast<const float4*>(bptr + (size_t)kt * CDIM);
        *reinterpret_cast<float4*>(&Bs[bkr][bjq]) = bv;
        __syncthreads();

#pragma unroll
        for (int k = 0; k < 8; k++) {
            float a[8], b[8];
#pragma unroll
            for (int i = 0; i < 8; i++) a[i] = As[k][ty * 8 + i];
#pragma unroll
            for (int j = 0; j < 8; j++) b[j] = Bs[k][tx * 8 + j];
#pragma unroll
            for (int i = 0; i < 8; i++)
#pragma unroll
                for (int j = 0; j < 8; j++) acc[i][j] += a[i] * b[j];
        }
        __syncthreads();
    }

#pragma unroll
    for (int i = 0; i < 8; i++) {
        int m = mt * 128 + ty * 8 + i;
        if (m >= T) continue;
        int tokn = g_bucket[e][m];
        float w  = g_wt[e][m];
        float* orow = out + (size_t)tokn * CDIM;
#pragma unroll
        for (int j = 0; j < 8; j++) {
            int jg = jt * 128 + tx * 8 + j;
            float val = w * (acc[i][j] + b2[e * CDIM + jg]);
            atomicAdd(&orow[jg], val);
        }
    }
}

// ---------------------------------------------------------------------------
// Launch
// ---------------------------------------------------------------------------
extern "C" void kernel_launch(void* const* d_in, const int* in_sizes, int n_in,
                              void* d_out, int out_size) {
    const float* x  = (const float*)d_in[0];
    const float* gw = (const float*)d_in[1];
    const float* w1 = (const float*)d_in[2];
    const float* b1 = (const float*)d_in[3];
    const float* w2 = (const float*)d_in[4];
    const float* b2 = (const float*)d_in[5];
    float* out = (float*)d_out;

    int total = NTOK * CDIM;
    zero_kernel<<<(total + 255) / 256, 256>>>(out);

    // one warp per token, 4 warps per block
    gate_kernel<<<NTOK / 4, 128>>>(x, gw);

    dim3 g1(HDIM / 128, NTOK / 128, NEXP);
    gemm1_kernel<<<g1, 256>>>(x, w1, b1);

    dim3 g2(CDIM / 128, NTOK / 128, NEXP);
    gemm2_kernel<<<g2, 256>>>(w2, b2, out);
}

// round 4
// speedup vs baseline: 2.0862x; 2.0862x over previous
#include <cuda_runtime.h>
#include <cuda_bf16.h>
#include <math.h>
#include <stdint.h>

#define NTOK 4096
#define CDIM 1024
#define HDIM 4096
#define NEXP 8

// ---------------------------------------------------------------------------
// Static device scratch (allocation-free per harness rules)
// ---------------------------------------------------------------------------
__device__ int   g_count[NEXP];
__device__ int   g_bucket[NEXP][NTOK];
__device__ float g_wt[NEXP][NTOK];

// bf16 split operand planes (hi + lo), K-major everywhere.
__device__ __align__(256) __nv_bfloat16 g_xg_hi[(size_t)NEXP * NTOK * CDIM];
__device__ __align__(256) __nv_bfloat16 g_xg_lo[(size_t)NEXP * NTOK * CDIM];
__device__ __align__(256) __nv_bfloat16 g_w1t_hi[(size_t)NEXP * HDIM * CDIM];
__device__ __align__(256) __nv_bfloat16 g_w1t_lo[(size_t)NEXP * HDIM * CDIM];
__device__ __align__(256) __nv_bfloat16 g_w2t_hi[(size_t)NEXP * CDIM * HDIM];
__device__ __align__(256) __nv_bfloat16 g_w2t_lo[(size_t)NEXP * CDIM * HDIM];
__device__ __align__(256) __nv_bfloat16 g_h_hi[(size_t)NEXP * NTOK * HDIM];
__device__ __align__(256) __nv_bfloat16 g_h_lo[(size_t)NEXP * NTOK * HDIM];

// ---------------------------------------------------------------------------
// PTX helpers (generic sm_80+ features only — no tcgen05 on this PTX target)
// ---------------------------------------------------------------------------
__device__ __forceinline__ uint32_t smem_u32(const void* p) {
    uint32_t a;
    asm("{ .reg .u64 t; cvta.to.shared.u64 t, %1; cvt.u32.u64 %0, t; }"
        : "=r"(a) : "l"(p));
    return a;
}
__device__ __forceinline__ void cpa16(uint32_t dst, const void* src) {
    asm volatile("cp.async.cg.shared.global [%0], [%1], 16;"
                 :: "r"(dst), "l"(src) : "memory");
}
__device__ __forceinline__ void cpa_commit() {
    asm volatile("cp.async.commit_group;" ::: "memory");
}
template <int N> __device__ __forceinline__ void cpa_wait() {
    asm volatile("cp.async.wait_group %0;" :: "n"(N) : "memory");
}
__device__ __forceinline__ void ldm_x4(uint32_t* r, uint32_t a) {
    asm volatile("ldmatrix.sync.aligned.m8n8.x4.shared.b16 {%0,%1,%2,%3}, [%4];"
                 : "=r"(r[0]), "=r"(r[1]), "=r"(r[2]), "=r"(r[3]) : "r"(a));
}
__device__ __forceinline__ void ldm_x2(uint32_t* r, uint32_t a) {
    asm volatile("ldmatrix.sync.aligned.m8n8.x2.shared.b16 {%0,%1}, [%2];"
                 : "=r"(r[0]), "=r"(r[1]) : "r"(a));
}
__device__ __forceinline__ void mma16816(float* c, const uint32_t* a, const uint32_t* b) {
    asm volatile(
        "mma.sync.aligned.m16n8k16.row.col.f32.bf16.bf16.f32 "
        "{%0,%1,%2,%3}, {%4,%5,%6,%7}, {%8,%9}, {%0,%1,%2,%3};"
        : "+f"(c[0]), "+f"(c[1]), "+f"(c[2]), "+f"(c[3])
        : "r"(a[0]), "r"(a[1]), "r"(a[2]), "r"(a[3]), "r"(b[0]), "r"(b[1]));
}

// ---------------------------------------------------------------------------
// Zero output + counters
// ---------------------------------------------------------------------------
__global__ void zero_kernel(float* __restrict__ out) {
    size_t i = (size_t)blockIdx.x * blockDim.x + threadIdx.x;
    if (i < (size_t)NTOK * CDIM) out[i] = 0.0f;
    if (i < NEXP) g_count[i] = 0;
}

// ---------------------------------------------------------------------------
// Gating: one warp per token
// ---------------------------------------------------------------------------
__global__ void gate_kernel(const float* __restrict__ x,
                            const float* __restrict__ gw) {
    int gtid = blockIdx.x * blockDim.x + threadIdx.x;
    int tok  = gtid >> 5;
    int lane = threadIdx.x & 31;
    if (tok >= NTOK) return;

    float p[NEXP];
#pragma unroll
    for (int e = 0; e < NEXP; e++) p[e] = 0.0f;
    const float* xr = x + (size_t)tok * CDIM;
    for (int k = lane; k < CDIM; k += 32) {
        float xv = xr[k];
        const float* gr = gw + (size_t)k * NEXP;
#pragma unroll
        for (int e = 0; e < NEXP; e++) p[e] += xv * gr[e];
    }
#pragma unroll
    for (int off = 16; off > 0; off >>= 1)
#pragma unroll
        for (int e = 0; e < NEXP; e++)
            p[e] += __shfl_xor_sync(0xFFFFFFFFu, p[e], off);
    if (lane == 0) {
        int e0 = 0;
#pragma unroll
        for (int e = 1; e < NEXP; e++) if (p[e] > p[e0]) e0 = e;
        int e1 = -1;
#pragma unroll
        for (int e = 0; e < NEXP; e++)
            if (e != e0 && (e1 < 0 || p[e] > p[e1])) e1 = e;
        float w0 = 1.0f / (1.0f + expf(p[e1] - p[e0]));
        float w1 = 1.0f - w0;
        int s0 = atomicAdd(&g_count[e0], 1);
        g_bucket[e0][s0] = tok; g_wt[e0][s0] = w0;
        int s1 = atomicAdd(&g_count[e1], 1);
        g_bucket[e1][s1] = tok; g_wt[e1][s1] = w1;
    }
}

// ---------------------------------------------------------------------------
// Gather + split x rows into per-expert bf16 hi/lo planes
// ---------------------------------------------------------------------------
__global__ void convert_x_kernel(const float* __restrict__ x) {
    const int e = blockIdx.y, slot = blockIdx.x;
    if (slot >= g_count[e]) return;
    const int tok = g_bucket[e][slot];
    const float4* src = reinterpret_cast<const float4*>(x + (size_t)tok * CDIM);
    const size_t rb = ((size_t)e * NTOK + slot) * CDIM;
    for (int i = threadIdx.x; i < CDIM / 4; i += blockDim.x) {
        float4 v = src[i];
        __nv_bfloat162 h0, h1, l0, l1;
        h0.x = __float2bfloat16(v.x); h0.y = __float2bfloat16(v.y);
        h1.x = __float2bfloat16(v.z); h1.y = __float2bfloat16(v.w);
        l0.x = __float2bfloat16(v.x - __bfloat162float(h0.x));
        l0.y = __float2bfloat16(v.y - __bfloat162float(h0.y));
        l1.x = __float2bfloat16(v.z - __bfloat162float(h1.x));
        l1.y = __float2bfloat16(v.w - __bfloat162float(h1.y));
        reinterpret_cast<__nv_bfloat162*>(g_xg_hi + rb)[2 * i]     = h0;
        reinterpret_cast<__nv_bfloat162*>(g_xg_hi + rb)[2 * i + 1] = h1;
        reinterpret_cast<__nv_bfloat162*>(g_xg_lo + rb)[2 * i]     = l0;
        reinterpret_cast<__nv_bfloat162*>(g_xg_lo + rb)[2 * i + 1] = l1;
    }
}

// ---------------------------------------------------------------------------
// Transpose + split weights: in [e][KD][ND] fp32 -> out [e][ND][KD] bf16 hi/lo
// ---------------------------------------------------------------------------
template <int KD, int ND, bool W1>
__global__ __launch_bounds__(256) void convert_w_kernel(const float* __restrict__ w) {
    __shared__ float tile[32][33];
    const int e = blockIdx.z;
    const float* we = w + (size_t)e * KD * ND;
    const int n0 = blockIdx.x * 32, k0 = blockIdx.y * 32;
    const int tx = threadIdx.x & 31, ty = threadIdx.x >> 5;  // ty 0..7
#pragma unroll
    for (int i = 0; i < 32; i += 8)
        tile[ty + i][tx] = we[(size_t)(k0 + ty + i) * ND + n0 + tx];
    __syncthreads();
    __nv_bfloat16* whi = W1 ? g_w1t_hi : g_w2t_hi;
    __nv_bfloat16* wlo = W1 ? g_w1t_lo : g_w2t_lo;
    const int px = threadIdx.x & 15, py = threadIdx.x >> 4;  // py 0..15
#pragma unroll
    for (int g = 0; g < 2; g++) {
        int r = py + g * 16;  // n-local
        float a = tile[2 * px][r], b = tile[2 * px + 1][r];
        __nv_bfloat162 hh, ll;
        hh.x = __float2bfloat16(a); hh.y = __float2bfloat16(b);
        ll.x = __float2bfloat16(a - __bfloat162float(hh.x));
        ll.y = __float2bfloat16(b - __bfloat162float(hh.y));
        size_t o = ((size_t)e * ND + n0 + r) * KD + k0 + 2 * px;
        *reinterpret_cast<__nv_bfloat162*>(whi + o) = hh;
        *reinterpret_cast<__nv_bfloat162*>(wlo + o) = ll;
    }
}

// ---------------------------------------------------------------------------
// Pipelined bf16 mma.sync GEMM.
// CTA tile 128x128, BK=32, 4 stages cp.async. 8 warps, each 64x32.
// Logical K = 3*KTOT via plane tables: A planes {hi, lo, hi}, B {hi, hi, lo}
// => acc = Ahi.Bhi + Alo.Bhi + Ahi.Blo  (fp32 accumulate).
// smem/stage: A 128x32 bf16 (8KB) + B 128x32 bf16 (8KB); XOR swizzle:
//   phys_chunk16 = chunk16 ^ ((row>>1)&3)   (conflict-free ldmatrix + stores)
// ---------------------------------------------------------------------------
#define GSTAGES 4
#define STAGE_B 16384
#define GSMEM   (GSTAGES * STAGE_B)

template <int KTOT, int NDIM, bool G1>
__global__ __launch_bounds__(256, 1) void moe_gemm_kernel(
    const float* __restrict__ bias, float* __restrict__ outp) {
    const int e = blockIdx.z, mt = blockIdx.y, jt = blockIdx.x;
    const int T = g_count[e];
    if (mt * 128 >= T) return;

    extern __shared__ __align__(1024) char smem[];
    const uint32_t sm = smem_u32(smem);
    const int tid = threadIdx.x, wid = tid >> 5, lane = tid & 31;
    const int warp_m = wid >> 2, warp_n = wid & 3;  // 2 x 4 warps

    constexpr int KC32 = KTOT / 32;
    constexpr int NCH = 3 * KC32;

    const __nv_bfloat16* aP[3];
    const __nv_bfloat16* bP[3];
    {
        const __nv_bfloat16* ahi =
            (G1 ? g_xg_hi : g_h_hi) + ((size_t)e * NTOK + mt * 128) * KTOT;
        const __nv_bfloat16* alo =
            (G1 ? g_xg_lo : g_h_lo) + ((size_t)e * NTOK + mt * 128) * KTOT;
        const __nv_bfloat16* bhi =
            (G1 ? g_w1t_hi : g_w2t_hi) + ((size_t)e * NDIM + jt * 128) * KTOT;
        const __nv_bfloat16* blo =
            (G1 ? g_w1t_lo : g_w2t_lo) + ((size_t)e * NDIM + jt * 128) * KTOT;
        aP[0] = ahi; aP[1] = alo; aP[2] = ahi;
        bP[0] = bhi; bP[1] = bhi; bP[2] = blo;
    }

    float acc[4][4][4];
#pragma unroll
    for (int mi = 0; mi < 4; mi++)
#pragma unroll
        for (int ni = 0; ni < 4; ni++)
#pragma unroll
            for (int r = 0; r < 4; r++) acc[mi][ni][r] = 0.0f;

    auto load_chunk = [&](int kc, int stg) {
        const int seg = kc / KC32;
        const int kk  = (kc - seg * KC32) * 32;
        const __nv_bfloat16* asrc = aP[seg] + kk;
        const __nv_bfloat16* bsrc = bP[seg] + kk;
        const uint32_t abase = sm + stg * STAGE_B;
        const uint32_t bbase = abase + 8192;
#pragma unroll
        for (int i = 0; i < 2; i++) {
            int u = tid + i * 256;
            int row = u >> 2, c = u & 3;
            int pc = c ^ ((row >> 1) & 3);
            cpa16(abase + row * 64 + pc * 16, asrc + (size_t)row * KTOT + c * 8);
        }
#pragma unroll
        for (int i = 0; i < 2; i++) {
            int u = tid + i * 256;
            int row = u >> 2, c = u & 3;
            int pc = c ^ ((row >> 1) & 3);
            cpa16(bbase + row * 64 + pc * 16, bsrc + (size_t)row * KTOT + c * 8);
        }
    };

    auto compute_stage = [&](int stg) {
        const uint32_t sA = sm + stg * STAGE_B;
        const uint32_t sB = sA + 8192;
#pragma unroll
        for (int s2 = 0; s2 < 2; s2++) {
            uint32_t a[4][4], b[4][2];
#pragma unroll
            for (int mi = 0; mi < 4; mi++) {
                int row = warp_m * 64 + mi * 16 + (lane & 15);
                int c = s2 * 2 + (lane >> 4);
                int pc = c ^ ((row >> 1) & 3);
                ldm_x4(a[mi], sA + row * 64 + pc * 16);
            }
#pragma unroll
            for (int ni = 0; ni < 4; ni++) {
                int row = warp_n * 32 + ni * 8 + (lane & 7);
                int c = s2 * 2 + ((lane >> 3) & 1);
                int pc = c ^ ((row >> 1) & 3);
                ldm_x2(b[ni], sB + row * 64 + pc * 16);
            }
#pragma unroll
            for (int mi = 0; mi < 4; mi++)
#pragma unroll
                for (int ni = 0; ni < 4; ni++)
                    mma16816(acc[mi][ni], a[mi], b[ni]);
        }
    };

    // prefetch
#pragma unroll
    for (int s = 0; s < GSTAGES - 1; s++) {
        load_chunk(s, s);
        cpa_commit();
    }
    for (int kc = 0; kc < NCH; kc++) {
        cpa_wait<GSTAGES - 2>();
        __syncthreads();
        const int nx = kc + GSTAGES - 1;
        if (nx < NCH) load_chunk(nx, nx & (GSTAGES - 1));
        cpa_commit();
        compute_stage(kc & (GSTAGES - 1));
    }

    // ----- epilogue -----
#pragma unroll
    for (int mi = 0; mi < 4; mi++) {
        const int m0 = mt * 128 + warp_m * 64 + mi * 16 + (lane >> 2);
#pragma unroll
        for (int half = 0; half < 2; half++) {
            const int m = m0 + half * 8;
            if (m >= T) continue;
            if (G1) {
                const size_t hrow = ((size_t)e * NTOK + m) * HDIM;
#pragma unroll
                for (int ni = 0; ni < 4; ni++) {
                    int n = jt * 128 + warp_n * 32 + ni * 8 + (lane & 3) * 2;
                    float v0 = acc[mi][ni][half * 2 + 0] + bias[e * NDIM + n];
                    float v1 = acc[mi][ni][half * 2 + 1] + bias[e * NDIM + n + 1];
                    float g0 = 0.5f * v0 * (1.0f + erff(v0 * 0.70710678118654752f));
                    float g1 = 0.5f * v1 * (1.0f + erff(v1 * 0.70710678118654752f));
                    __nv_bfloat162 hh, ll;
                    hh.x = __float2bfloat16(g0); hh.y = __float2bfloat16(g1);
                    ll.x = __float2bfloat16(g0 - __bfloat162float(hh.x));
                    ll.y = __float2bfloat16(g1 - __bfloat162float(hh.y));
                    *reinterpret_cast<__nv_bfloat162*>(g_h_hi + hrow + n) = hh;
                    *reinterpret_cast<__nv_bfloat162*>(g_h_lo + hrow + n) = ll;
                }
            } else {
                const int tokn = g_bucket[e][m];
                const float wc = g_wt[e][m];
                float* orow = outp + (size_t)tokn * CDIM;
#pragma unroll
                for (int ni = 0; ni < 4; ni++) {
                    int n = jt * 128 + warp_n * 32 + ni * 8 + (lane & 3) * 2;
                    float v0 = acc[mi][ni][half * 2 + 0] + bias[e * NDIM + n];
                    float v1 = acc[mi][ni][half * 2 + 1] + bias[e * NDIM + n + 1];
                    atomicAdd(orow + n, wc * v0);
                    atomicAdd(orow + n + 1, wc * v1);
                }
            }
        }
    }
}

// ---------------------------------------------------------------------------
// Launch
// ---------------------------------------------------------------------------
extern "C" void kernel_launch(void* const* d_in, const int* in_sizes, int n_in,
                              void* d_out, int out_size) {
    const float* x  = (const float*)d_in[0];
    const float* gw = (const float*)d_in[1];
    const float* w1 = (const float*)d_in[2];
    const float* b1 = (const float*)d_in[3];
    const float* w2 = (const float*)d_in[4];
    const float* b2 = (const float*)d_in[5];
    float* out = (float*)d_out;

    cudaFuncSetAttribute((const void*)moe_gemm_kernel<CDIM, HDIM, true>,
                         cudaFuncAttributeMaxDynamicSharedMemorySize, GSMEM);
    cudaFuncSetAttribute((const void*)moe_gemm_kernel<HDIM, CDIM, false>,
                         cudaFuncAttributeMaxDynamicSharedMemorySize, GSMEM);

    zero_kernel<<<(NTOK * CDIM + 255) / 256, 256>>>(out);
    gate_kernel<<<NTOK / 4, 128>>>(x, gw);
    convert_x_kernel<<<dim3(NTOK, NEXP), 128>>>(x);
    convert_w_kernel<CDIM, HDIM, true><<<dim3(HDIM / 32, CDIM / 32, NEXP), 256>>>(w1);
    convert_w_kernel<HDIM, CDIM, false><<<dim3(CDIM / 32, HDIM / 32, NEXP), 256>>>(w2);

    moe_gemm_kernel<CDIM, HDIM, true>
        <<<dim3(HDIM / 128, NTOK / 128, NEXP), 256, GSMEM>>>(b1, nullptr);
    moe_gemm_kernel<HDIM, CDIM, false>
        <<<dim3(CDIM / 128, NTOK / 128, NEXP), 256, GSMEM>>>(b2, out);
}

// round 5
// speedup vs baseline: 5.1163x; 2.4525x over previous
#include <cuda_runtime.h>
#include <cuda_fp16.h>
#include <math.h>
#include <stdint.h>

#define NTOK 4096
#define CDIM 1024
#define HDIM 4096
#define NEXP 8

// ---------------------------------------------------------------------------
// Static device scratch (allocation-free per harness rules)
// ---------------------------------------------------------------------------
__device__ int   g_count[NEXP];
__device__ int   g_bucket[NEXP][NTOK];
__device__ float g_wt[NEXP][NTOK];

// fp16 operand planes, K-major everywhere.
__device__ __align__(256) __half g_xg[(size_t)NEXP * NTOK * CDIM];
__device__ __align__(256) __half g_w1t[(size_t)NEXP * HDIM * CDIM];
__device__ __align__(256) __half g_w2t[(size_t)NEXP * CDIM * HDIM];
__device__ __align__(256) __half g_h[(size_t)NEXP * NTOK * HDIM];

// ---------------------------------------------------------------------------
// PTX helpers (generic sm_80+ features only — no tcgen05 on this PTX target)
// ---------------------------------------------------------------------------
__device__ __forceinline__ uint32_t smem_u32(const void* p) {
    uint32_t a;
    asm("{ .reg .u64 t; cvta.to.shared.u64 t, %1; cvt.u32.u64 %0, t; }"
        : "=r"(a) : "l"(p));
    return a;
}
__device__ __forceinline__ void cpa16(uint32_t dst, const void* src) {
    asm volatile("cp.async.cg.shared.global [%0], [%1], 16;"
                 :: "r"(dst), "l"(src) : "memory");
}
__device__ __forceinline__ void cpa_commit() {
    asm volatile("cp.async.commit_group;" ::: "memory");
}
template <int N> __device__ __forceinline__ void cpa_wait() {
    asm volatile("cp.async.wait_group %0;" :: "n"(N) : "memory");
}
__device__ __forceinline__ void ldm_x4(uint32_t* r, uint32_t a) {
    asm volatile("ldmatrix.sync.aligned.m8n8.x4.shared.b16 {%0,%1,%2,%3}, [%4];"
                 : "=r"(r[0]), "=r"(r[1]), "=r"(r[2]), "=r"(r[3]) : "r"(a));
}
__device__ __forceinline__ void ldm_x2(uint32_t* r, uint32_t a) {
    asm volatile("ldmatrix.sync.aligned.m8n8.x2.shared.b16 {%0,%1}, [%2];"
                 : "=r"(r[0]), "=r"(r[1]) : "r"(a));
}
__device__ __forceinline__ void mma16816(float* c, const uint32_t* a, const uint32_t* b) {
    asm volatile(
        "mma.sync.aligned.m16n8k16.row.col.f32.f16.f16.f32 "
        "{%0,%1,%2,%3}, {%4,%5,%6,%7}, {%8,%9}, {%0,%1,%2,%3};"
        : "+f"(c[0]), "+f"(c[1]), "+f"(c[2]), "+f"(c[3])
        : "r"(a[0]), "r"(a[1]), "r"(a[2]), "r"(a[3]), "r"(b[0]), "r"(b[1]));
}

// ---------------------------------------------------------------------------
// Zero output + counters
// ---------------------------------------------------------------------------
__global__ void zero_kernel(float* __restrict__ out) {
    size_t i = (size_t)blockIdx.x * blockDim.x + threadIdx.x;
    if (i < (size_t)NTOK * CDIM) out[i] = 0.0f;
    if (i < NEXP) g_count[i] = 0;
}

// ---------------------------------------------------------------------------
// Gating: one warp per token
// ---------------------------------------------------------------------------
__global__ void gate_kernel(const float* __restrict__ x,
                            const float* __restrict__ gw) {
    int gtid = blockIdx.x * blockDim.x + threadIdx.x;
    int tok  = gtid >> 5;
    int lane = threadIdx.x & 31;
    if (tok >= NTOK) return;

    float p[NEXP];
#pragma unroll
    for (int e = 0; e < NEXP; e++) p[e] = 0.0f;
    const float* xr = x + (size_t)tok * CDIM;
    for (int k = lane; k < CDIM; k += 32) {
        float xv = xr[k];
        const float* gr = gw + (size_t)k * NEXP;
#pragma unroll
        for (int e = 0; e < NEXP; e++) p[e] += xv * gr[e];
    }
#pragma unroll
    for (int off = 16; off > 0; off >>= 1)
#pragma unroll
        for (int e = 0; e < NEXP; e++)
            p[e] += __shfl_xor_sync(0xFFFFFFFFu, p[e], off);
    if (lane == 0) {
        int e0 = 0;
#pragma unroll
        for (int e = 1; e < NEXP; e++) if (p[e] > p[e0]) e0 = e;
        int e1 = -1;
#pragma unroll
        for (int e = 0; e < NEXP; e++)
            if (e != e0 && (e1 < 0 || p[e] > p[e1])) e1 = e;
        float w0 = 1.0f / (1.0f + expf(p[e1] - p[e0]));
        float w1 = 1.0f - w0;
        int s0 = atomicAdd(&g_count[e0], 1);
        g_bucket[e0][s0] = tok; g_wt[e0][s0] = w0;
        int s1 = atomicAdd(&g_count[e1], 1);
        g_bucket[e1][s1] = tok; g_wt[e1][s1] = w1;
    }
}

// ---------------------------------------------------------------------------
// Gather + convert x rows into per-expert fp16 planes
// ---------------------------------------------------------------------------
__global__ void convert_x_kernel(const float* __restrict__ x) {
    const int e = blockIdx.y, slot = blockIdx.x;
    if (slot >= g_count[e]) return;
    const int tok = g_bucket[e][slot];
    const float4* src = reinterpret_cast<const float4*>(x + (size_t)tok * CDIM);
    __half2* dst = reinterpret_cast<__half2*>(g_xg + ((size_t)e * NTOK + slot) * CDIM);
    for (int i = threadIdx.x; i < CDIM / 4; i += blockDim.x) {
        float4 v = src[i];
        dst[2 * i]     = __floats2half2_rn(v.x, v.y);
        dst[2 * i + 1] = __floats2half2_rn(v.z, v.w);
    }
}

// ---------------------------------------------------------------------------
// Transpose + convert weights: in [e][KD][ND] fp32 -> out [e][ND][KD] fp16
// ---------------------------------------------------------------------------
template <int KD, int ND, bool W1>
__global__ __launch_bounds__(256) void convert_w_kernel(const float* __restrict__ w) {
    __shared__ float tile[32][33];
    const int e = blockIdx.z;
    const float* we = w + (size_t)e * KD * ND;
    const int n0 = blockIdx.x * 32, k0 = blockIdx.y * 32;
    const int tx = threadIdx.x & 31, ty = threadIdx.x >> 5;  // ty 0..7
#pragma unroll
    for (int i = 0; i < 32; i += 8)
        tile[ty + i][tx] = we[(size_t)(k0 + ty + i) * ND + n0 + tx];
    __syncthreads();
    __half* wt = W1 ? g_w1t : g_w2t;
    const int px = threadIdx.x & 15, py = threadIdx.x >> 4;  // py 0..15
#pragma unroll
    for (int g = 0; g < 2; g++) {
        int r = py + g * 16;  // n-local
        float a = tile[2 * px][r], b = tile[2 * px + 1][r];
        size_t o = ((size_t)e * ND + n0 + r) * KD + k0 + 2 * px;
        *reinterpret_cast<__half2*>(wt + o) = __floats2half2_rn(a, b);
    }
}

// ---------------------------------------------------------------------------
// Pipelined fp16 mma.sync GEMM.
// CTA tile 128x128, BK=32, 4 stages cp.async. 8 warps, each 64x32.
// fp32 accumulate. smem/stage: A 128x32 (8KB) + B 128x32 (8KB); XOR swizzle:
//   phys_chunk16 = chunk16 ^ ((row>>1)&3)   (conflict-free ldmatrix + stores)
// ---------------------------------------------------------------------------
#define GSTAGES 4
#define STAGE_B 16384
#define GSMEM   (GSTAGES * STAGE_B)

template <int KTOT, int NDIM, bool G1>
__global__ __launch_bounds__(256, 1) void moe_gemm_kernel(
    const float* __restrict__ bias, float* __restrict__ outp) {
    const int e = blockIdx.z, mt = blockIdx.y, jt = blockIdx.x;
    const int T = g_count[e];
    if (mt * 128 >= T) return;

    extern __shared__ __align__(1024) char smem[];
    const uint32_t sm = smem_u32(smem);
    const int tid = threadIdx.x, wid = tid >> 5, lane = tid & 31;
    const int warp_m = wid >> 2, warp_n = wid & 3;  // 2 x 4 warps

    constexpr int NCH = KTOT / 32;

    const __half* aBase =
        (G1 ? g_xg : g_h) + ((size_t)e * NTOK + mt * 128) * KTOT;
    const __half* bBase =
        (G1 ? g_w1t : g_w2t) + ((size_t)e * NDIM + jt * 128) * KTOT;

    float acc[4][4][4];
#pragma unroll
    for (int mi = 0; mi < 4; mi++)
#pragma unroll
        for (int ni = 0; ni < 4; ni++)
#pragma unroll
            for (int r = 0; r < 4; r++) acc[mi][ni][r] = 0.0f;

    auto load_chunk = [&](int kc, int stg) {
        const int kk = kc * 32;
        const __half* asrc = aBase + kk;
        const __half* bsrc = bBase + kk;
        const uint32_t abase = sm + stg * STAGE_B;
        const uint32_t bbase = abase + 8192;
#pragma unroll
        for (int i = 0; i < 2; i++) {
            int u = tid + i * 256;
            int row = u >> 2, c = u & 3;
            int pc = c ^ ((row >> 1) & 3);
            cpa16(abase + row * 64 + pc * 16, asrc + (size_t)row * KTOT + c * 8);
        }
#pragma unroll
        for (int i = 0; i < 2; i++) {
            int u = tid + i * 256;
            int row = u >> 2, c = u & 3;
            int pc = c ^ ((row >> 1) & 3);
            cpa16(bbase + row * 64 + pc * 16, bsrc + (size_t)row * KTOT + c * 8);
        }
    };

    auto compute_stage = [&](int stg) {
        const uint32_t sA = sm + stg * STAGE_B;
        const uint32_t sB = sA + 8192;
#pragma unroll
        for (int s2 = 0; s2 < 2; s2++) {
            uint32_t a[4][4], b[4][2];
#pragma unroll
            for (int mi = 0; mi < 4; mi++) {
                int row = warp_m * 64 + mi * 16 + (lane & 15);
                int c = s2 * 2 + (lane >> 4);
                int pc = c ^ ((row >> 1) & 3);
                ldm_x4(a[mi], sA + row * 64 + pc * 16);
            }
#pragma unroll
            for (int ni = 0; ni < 4; ni++) {
                int row = warp_n * 32 + ni * 8 + (lane & 7);
                int c = s2 * 2 + ((lane >> 3) & 1);
                int pc = c ^ ((row >> 1) & 3);
                ldm_x2(b[ni], sB + row * 64 + pc * 16);
            }
#pragma unroll
            for (int mi = 0; mi < 4; mi++)
#pragma unroll
                for (int ni = 0; ni < 4; ni++)
                    mma16816(acc[mi][ni], a[mi], b[ni]);
        }
    };

    // prefetch
#pragma unroll
    for (int s = 0; s < GSTAGES - 1; s++) {
        load_chunk(s, s);
        cpa_commit();
    }
    for (int kc = 0; kc < NCH; kc++) {
        cpa_wait<GSTAGES - 2>();
        __syncthreads();
        const int nx = kc + GSTAGES - 1;
        if (nx < NCH) load_chunk(nx, nx & (GSTAGES - 1));
        cpa_commit();
        compute_stage(kc & (GSTAGES - 1));
    }

    // ----- epilogue -----
#pragma unroll
    for (int mi = 0; mi < 4; mi++) {
        const int m0 = mt * 128 + warp_m * 64 + mi * 16 + (lane >> 2);
#pragma unroll
        for (int half = 0; half < 2; half++) {
            const int m = m0 + half * 8;
            if (m >= T) continue;
            if (G1) {
                const size_t hrow = ((size_t)e * NTOK + m) * HDIM;
#pragma unroll
                for (int ni = 0; ni < 4; ni++) {
                    int n = jt * 128 + warp_n * 32 + ni * 8 + (lane & 3) * 2;
                    float v0 = acc[mi][ni][half * 2 + 0] + bias[e * NDIM + n];
                    float v1 = acc[mi][ni][half * 2 + 1] + bias[e * NDIM + n + 1];
                    float g0 = 0.5f * v0 * (1.0f + erff(v0 * 0.70710678118654752f));
                    float g1 = 0.5f * v1 * (1.0f + erff(v1 * 0.70710678118654752f));
                    *reinterpret_cast<__half2*>(g_h + hrow + n) =
                        __floats2half2_rn(g0, g1);
                }
            } else {
                const int tokn = g_bucket[e][m];
                const float wc = g_wt[e][m];
                float* orow = outp + (size_t)tokn * CDIM;
#pragma unroll
                for (int ni = 0; ni < 4; ni++) {
                    int n = jt * 128 + warp_n * 32 + ni * 8 + (lane & 3) * 2;
                    float v0 = acc[mi][ni][half * 2 + 0] + bias[e * NDIM + n];
                    float v1 = acc[mi][ni][half * 2 + 1] + bias[e * NDIM + n + 1];
                    atomicAdd(orow + n, wc * v0);
                    atomicAdd(orow + n + 1, wc * v1);
                }
            }
        }
    }
}

// ---------------------------------------------------------------------------
// Launch
// ---------------------------------------------------------------------------
extern "C" void kernel_launch(void* const* d_in, const int* in_sizes, int n_in,
                              void* d_out, int out_size) {
    const float* x  = (const float*)d_in[0];
    const float* gw = (const float*)d_in[1];
    const float* w1 = (const float*)d_in[2];
    const float* b1 = (const float*)d_in[3];
    const float* w2 = (const float*)d_in[4];
    const float* b2 = (const float*)d_in[5];
    float* out = (float*)d_out;

    cudaFuncSetAttribute((const void*)moe_gemm_kernel<CDIM, HDIM, true>,
                         cudaFuncAttributeMaxDynamicSharedMemorySize, GSMEM);
    cudaFuncSetAttribute((const void*)moe_gemm_kernel<HDIM, CDIM, false>,
                         cudaFuncAttributeMaxDynamicSharedMemorySize, GSMEM);

    zero_kernel<<<(NTOK * CDIM + 255) / 256, 256>>>(out);
    gate_kernel<<<NTOK / 4, 128>>>(x, gw);
    convert_x_kernel<<<dim3(NTOK, NEXP), 128>>>(x);
    convert_w_kernel<CDIM, HDIM, true><<<dim3(HDIM / 32, CDIM / 32, NEXP), 256>>>(w1);
    convert_w_kernel<HDIM, CDIM, false><<<dim3(CDIM / 32, HDIM / 32, NEXP), 256>>>(w2);

    moe_gemm_kernel<CDIM, HDIM, true>
        <<<dim3(HDIM / 128, NTOK / 128, NEXP), 256, GSMEM>>>(b1, nullptr);
    moe_gemm_kernel<HDIM, CDIM, false>
        <<<dim3(CDIM / 128, NTOK / 128, NEXP), 256, GSMEM>>>(b2, out);
}

// round 9
// speedup vs baseline: 5.7918x; 1.1320x over previous
#include <cuda_runtime.h>
#include <cuda_fp16.h>
#include <math.h>
#include <stdint.h>

#define NTOK 4096
#define CDIM 1024
#define HDIM 4096
#define NEXP 8

// ---------------------------------------------------------------------------
// Static device scratch (allocation-free per harness rules)
// ---------------------------------------------------------------------------
__device__ int   g_count[NEXP];
__device__ int   g_bucket[NEXP][NTOK];
__device__ float g_wt[NEXP][NTOK];

// fp16 operand planes, K-major everywhere.
__device__ __align__(256) __half g_xg[(size_t)NEXP * NTOK * CDIM];
__device__ __align__(256) __half g_w1t[(size_t)NEXP * HDIM * CDIM];
__device__ __align__(256) __half g_w2t[(size_t)NEXP * CDIM * HDIM];
__device__ __align__(256) __half g_h[(size_t)NEXP * NTOK * HDIM];

// ---------------------------------------------------------------------------
// PTX helpers (generic sm_80+ features only — no tcgen05 on this PTX target)
// ---------------------------------------------------------------------------
__device__ __forceinline__ uint32_t smem_u32(const void* p) {
    uint32_t a;
    asm("{ .reg .u64 t; cvta.to.shared.u64 t, %1; cvt.u32.u64 %0, t; }"
        : "=r"(a) : "l"(p));
    return a;
}
__device__ __forceinline__ void cpa16(uint32_t dst, const void* src) {
    asm volatile("cp.async.cg.shared.global [%0], [%1], 16;"
                 :: "r"(dst), "l"(src) : "memory");
}
__device__ __forceinline__ void cpa_commit() {
    asm volatile("cp.async.commit_group;" ::: "memory");
}
template <int N> __device__ __forceinline__ void cpa_wait() {
    asm volatile("cp.async.wait_group %0;" :: "n"(N) : "memory");
}
__device__ __forceinline__ void ldm_x4(uint32_t* r, uint32_t a) {
    asm volatile("ldmatrix.sync.aligned.m8n8.x4.shared.b16 {%0,%1,%2,%3}, [%4];"
                 : "=r"(r[0]), "=r"(r[1]), "=r"(r[2]), "=r"(r[3]) : "r"(a));
}
__device__ __forceinline__ void ldm_x2(uint32_t* r, uint32_t a) {
    asm volatile("ldmatrix.sync.aligned.m8n8.x2.shared.b16 {%0,%1}, [%2];"
                 : "=r"(r[0]), "=r"(r[1]) : "r"(a));
}
__device__ __forceinline__ void mma16816(float* c, const uint32_t* a, const uint32_t* b) {
    asm volatile(
        "mma.sync.aligned.m16n8k16.row.col.f32.f16.f16.f32 "
        "{%0,%1,%2,%3}, {%4,%5,%6,%7}, {%8,%9}, {%0,%1,%2,%3};"
        : "+f"(c[0]), "+f"(c[1]), "+f"(c[2]), "+f"(c[3])
        : "r"(a[0]), "r"(a[1]), "r"(a[2]), "r"(a[3]), "r"(b[0]), "r"(b[1]));
}

// ---------------------------------------------------------------------------
// Zero output + counters
// ---------------------------------------------------------------------------
__global__ void zero_kernel(float* __restrict__ out) {
    size_t i = (size_t)blockIdx.x * blockDim.x + threadIdx.x;
    if (i < (size_t)NTOK * CDIM) out[i] = 0.0f;
    if (i < NEXP) g_count[i] = 0;
}

// ---------------------------------------------------------------------------
// Gating: one warp per token
// ---------------------------------------------------------------------------
__global__ void gate_kernel(const float* __restrict__ x,
                            const float* __restrict__ gw) {
    int gtid = blockIdx.x * blockDim.x + threadIdx.x;
    int tok  = gtid >> 5;
    int lane = threadIdx.x & 31;
    if (tok >= NTOK) return;

    float p[NEXP];
#pragma unroll
    for (int e = 0; e < NEXP; e++) p[e] = 0.0f;
    const float* xr = x + (size_t)tok * CDIM;
    for (int k = lane; k < CDIM; k += 32) {
        float xv = xr[k];
        const float* gr = gw + (size_t)k * NEXP;
#pragma unroll
        for (int e = 0; e < NEXP; e++) p[e] += xv * gr[e];
    }
#pragma unroll
    for (int off = 16; off > 0; off >>= 1)
#pragma unroll
        for (int e = 0; e < NEXP; e++)
            p[e] += __shfl_xor_sync(0xFFFFFFFFu, p[e], off);
    if (lane == 0) {
        int e0 = 0;
#pragma unroll
        for (int e = 1; e < NEXP; e++) if (p[e] > p[e0]) e0 = e;
        int e1 = -1;
#pragma unroll
        for (int e = 0; e < NEXP; e++)
            if (e != e0 && (e1 < 0 || p[e] > p[e1])) e1 = e;
        float w0 = 1.0f / (1.0f + expf(p[e1] - p[e0]));
        float w1 = 1.0f - w0;
        int s0 = atomicAdd(&g_count[e0], 1);
        g_bucket[e0][s0] = tok; g_wt[e0][s0] = w0;
        int s1 = atomicAdd(&g_count[e1], 1);
        g_bucket[e1][s1] = tok; g_wt[e1][s1] = w1;
    }
}

// ---------------------------------------------------------------------------
// Gather + convert x rows into per-expert fp16 planes
// ---------------------------------------------------------------------------
__global__ void convert_x_kernel(const float* __restrict__ x) {
    const int e = blockIdx.y, slot = blockIdx.x;
    if (slot >= g_count[e]) return;
    const int tok = g_bucket[e][slot];
    const float4* src = reinterpret_cast<const float4*>(x + (size_t)tok * CDIM);
    __half2* dst = reinterpret_cast<__half2*>(g_xg + ((size_t)e * NTOK + slot) * CDIM);
    for (int i = threadIdx.x; i < CDIM / 4; i += blockDim.x) {
        float4 v = src[i];
        dst[2 * i]     = __floats2half2_rn(v.x, v.y);
        dst[2 * i + 1] = __floats2half2_rn(v.z, v.w);
    }
}

// ---------------------------------------------------------------------------
// Transpose + convert weights: in [e][KD][ND] fp32 -> out [e][ND][KD] fp16
// ---------------------------------------------------------------------------
template <int KD, int ND, bool W1>
__global__ __launch_bounds__(256) void convert_w_kernel(const float* __restrict__ w) {
    __shared__ float tile[32][33];
    const int e = blockIdx.z;
    const float* we = w + (size_t)e * KD * ND;
    const int n0 = blockIdx.x * 32, k0 = blockIdx.y * 32;
    const int tx = threadIdx.x & 31, ty = threadIdx.x >> 5;  // ty 0..7
#pragma unroll
    for (int i = 0; i < 32; i += 8)
        tile[ty + i][tx] = we[(size_t)(k0 + ty + i) * ND + n0 + tx];
    __syncthreads();
    __half* wt = W1 ? g_w1t : g_w2t;
    const int px = threadIdx.x & 15, py = threadIdx.x >> 4;  // py 0..15
#pragma unroll
    for (int g = 0; g < 2; g++) {
        int r = py + g * 16;  // n-local
        float a = tile[2 * px][r], b = tile[2 * px + 1][r];
        size_t o = ((size_t)e * ND + n0 + r) * KD + k0 + 2 * px;
        *reinterpret_cast<__half2*>(wt + o) = __floats2half2_rn(a, b);
    }
}

// ---------------------------------------------------------------------------
// Pipelined fp16 mma.sync GEMM.
// CTA tile 128x128, BK=64, 2 stages (64KB total — same smem footprint as the
// known-good R5 kernel; 3 CTAs/SM). Register double-buffered fragments.
// 8 warps, each 64x32. fp32 accumulate.
// smem/stage: A 128x64 (16KB) + B 128x64 (16KB). 128B rows, 8 chunks of 16B:
//   phys_chunk = chunk ^ (row & 7)   (conflict-free stores + ldmatrix)
// Schedule per iter kc: wait chunk kc; compute kc (frag double-buffered);
// sync; prefetch kc+2 into the stage kc just vacated.
// ---------------------------------------------------------------------------
#define GSTAGES 2
#define STAGE_B 32768
#define GSMEM   (GSTAGES * STAGE_B)

template <int KTOT, int NDIM, bool G1>
__global__ __launch_bounds__(256, 1) void moe_gemm_kernel(
    const float* __restrict__ bias, float* __restrict__ outp) {
    const int e = blockIdx.z, mt = blockIdx.y, jt = blockIdx.x;
    const int T = g_count[e];
    if (mt * 128 >= T) return;

    extern __shared__ __align__(1024) char smem[];
    const uint32_t sm = smem_u32(smem);
    const int tid = threadIdx.x, wid = tid >> 5, lane = tid & 31;
    const int warp_m = wid >> 2, warp_n = wid & 3;  // 2 x 4 warps

    constexpr int NC = KTOT / 64;

    const __half* aBase =
        (G1 ? g_xg : g_h) + ((size_t)e * NTOK + mt * 128) * KTOT;
    const __half* bBase =
        (G1 ? g_w1t : g_w2t) + ((size_t)e * NDIM + jt * 128) * KTOT;

    float acc[4][4][4];
#pragma unroll
    for (int mi = 0; mi < 4; mi++)
#pragma unroll
        for (int ni = 0; ni < 4; ni++)
#pragma unroll
            for (int r = 0; r < 4; r++) acc[mi][ni][r] = 0.0f;

    // load one 128x64 A tile + 128x64 B tile (each 1024 x 16B units)
    auto load_chunk = [&](int kc, int stg) {
        const int kk = kc * 64;
        const __half* asrc = aBase + kk;
        const __half* bsrc = bBase + kk;
        const uint32_t abase = sm + stg * STAGE_B;
        const uint32_t bbase = abase + 16384;
#pragma unroll
        for (int i = 0; i < 4; i++) {
            int u = tid + i * 256;
            int row = u >> 3, c = u & 7;
            int pc = c ^ (row & 7);
            cpa16(abase + row * 128 + pc * 16, asrc + (size_t)row * KTOT + c * 8);
        }
#pragma unroll
        for (int i = 0; i < 4; i++) {
            int u = tid + i * 256;
            int row = u >> 3, c = u & 7;
            int pc = c ^ (row & 7);
            cpa16(bbase + row * 128 + pc * 16, bsrc + (size_t)row * KTOT + c * 8);
        }
        cpa_commit();
    };

    // load register fragments for k-half kh (0..3) of stage stg
    auto frag_load = [&](int stg, int kh, uint32_t a[4][4], uint32_t b[4][2]) {
        const uint32_t sA = sm + stg * STAGE_B;
        const uint32_t sB = sA + 16384;
#pragma unroll
        for (int mi = 0; mi < 4; mi++) {
            int row = warp_m * 64 + mi * 16 + (lane & 15);
            int c = kh * 2 + (lane >> 4);
            int pc = c ^ (row & 7);
            ldm_x4(a[mi], sA + row * 128 + pc * 16);
        }
#pragma unroll
        for (int ni = 0; ni < 4; ni++) {
            int row = warp_n * 32 + ni * 8 + (lane & 7);
            int c = kh * 2 + ((lane >> 3) & 1);
            int pc = c ^ (row & 7);
            ldm_x2(b[ni], sB + row * 128 + pc * 16);
        }
    };

    uint32_t af[2][4][4], bf[2][4][2];

    // prologue: prefetch chunks 0 and 1 into stages 0 and 1
    load_chunk(0, 0);
    if (NC > 1) load_chunk(1, 1);

    for (int kc = 0; kc < NC; kc++) {
        const int stg = kc & 1;
        // wait until chunk kc is resident (allow the younger group in flight)
        if (kc + 1 < NC) cpa_wait<1>(); else cpa_wait<0>();
        __syncthreads();
        frag_load(stg, 0, af[0], bf[0]);
#pragma unroll
        for (int kh = 0; kh < 4; kh++) {
            if (kh < 3) frag_load(stg, kh + 1, af[(kh + 1) & 1], bf[(kh + 1) & 1]);
            uint32_t (*a)[4] = af[kh & 1];
            uint32_t (*b)[2] = bf[kh & 1];
#pragma unroll
            for (int mi = 0; mi < 4; mi++)
#pragma unroll
                for (int ni = 0; ni < 4; ni++)
                    mma16816(acc[mi][ni], a[mi], b[ni]);
        }
        // stage stg fully consumed; refill it with chunk kc+2
        if (kc + 2 < NC) {
            __syncthreads();
            load_chunk(kc + 2, stg);
        }
    }

    // ----- epilogue -----
#pragma unroll
    for (int mi = 0; mi < 4; mi++) {
        const int m0 = mt * 128 + warp_m * 64 + mi * 16 + (lane >> 2);
#pragma unroll
        for (int half = 0; half < 2; half++) {
            const int m = m0 + half * 8;
            if (m >= T) continue;
            if (G1) {
                const size_t hrow = ((size_t)e * NTOK + m) * HDIM;
#pragma unroll
                for (int ni = 0; ni < 4; ni++) {
                    int n = jt * 128 + warp_n * 32 + ni * 8 + (lane & 3) * 2;
                    float v0 = acc[mi][ni][half * 2 + 0] + bias[e * NDIM + n];
                    float v1 = acc[mi][ni][half * 2 + 1] + bias[e * NDIM + n + 1];
                    float g0 = 0.5f * v0 * (1.0f + erff(v0 * 0.70710678118654752f));
                    float g1 = 0.5f * v1 * (1.0f + erff(v1 * 0.70710678118654752f));
                    *reinterpret_cast<__half2*>(g_h + hrow + n) =
                        __floats2half2_rn(g0, g1);
                }
            } else {
                const int tokn = g_bucket[e][m];
                const float wc = g_wt[e][m];
                float* orow = outp + (size_t)tokn * CDIM;
#pragma unroll
                for (int ni = 0; ni < 4; ni++) {
                    int n = jt * 128 + warp_n * 32 + ni * 8 + (lane & 3) * 2;
                    float v0 = acc[mi][ni][half * 2 + 0] + bias[e * NDIM + n];
                    float v1 = acc[mi][ni][half * 2 + 1] + bias[e * NDIM + n + 1];
                    atomicAdd(orow + n, wc * v0);
                    atomicAdd(orow + n + 1, wc * v1);
                }
            }
        }
    }
}

// ---------------------------------------------------------------------------
// Launch
// ---------------------------------------------------------------------------
extern "C" void kernel_launch(void* const* d_in, const int* in_sizes, int n_in,
                              void* d_out, int out_size) {
    const float* x  = (const float*)d_in[0];
    const float* gw = (const float*)d_in[1];
    const float* w1 = (const float*)d_in[2];
    const float* b1 = (const float*)d_in[3];
    const float* w2 = (const float*)d_in[4];
    const float* b2 = (const float*)d_in[5];
    float* out = (float*)d_out;

    cudaFuncSetAttribute((const void*)moe_gemm_kernel<CDIM, HDIM, true>,
                         cudaFuncAttributeMaxDynamicSharedMemorySize, GSMEM);
    cudaFuncSetAttribute((const void*)moe_gemm_kernel<HDIM, CDIM, false>,
                         cudaFuncAttributeMaxDynamicSharedMemorySize, GSMEM);

    zero_kernel<<<(NTOK * CDIM + 255) / 256, 256>>>(out);
    gate_kernel<<<NTOK / 4, 128>>>(x, gw);
    convert_x_kernel<<<dim3(NTOK, NEXP), 128>>>(x);
    convert_w_kernel<CDIM, HDIM, true><<<dim3(HDIM / 32, CDIM / 32, NEXP), 256>>>(w1);
    convert_w_kernel<HDIM, CDIM, false><<<dim3(CDIM / 32, HDIM / 32, NEXP), 256>>>(w2);

    moe_gemm_kernel<CDIM, HDIM, true>
        <<<dim3(HDIM / 128, NTOK / 128, NEXP), 256, GSMEM>>>(b1, nullptr);
    moe_gemm_kernel<HDIM, CDIM, false>
        <<<dim3(CDIM / 128, NTOK / 128, NEXP), 256, GSMEM>>>(b2, out);
}

// round 12
// speedup vs baseline: 5.8365x; 1.0077x over previous
#include <cuda_runtime.h>
#include <cuda_fp16.h>
#include <math.h>
#include <stdint.h>

#define NTOK 4096
#define CDIM 1024
#define HDIM 4096
#define NEXP 8

// ---------------------------------------------------------------------------
// Static device scratch (allocation-free per harness rules)
// ---------------------------------------------------------------------------
__device__ int   g_count[NEXP];
__device__ int   g_bucket[NEXP][NTOK];
__device__ float g_wt[NEXP][NTOK];

// fp16 operand planes, K-major everywhere.
__device__ __align__(256) __half g_xg[(size_t)NEXP * NTOK * CDIM];
__device__ __align__(256) __half g_w1t[(size_t)NEXP * HDIM * CDIM];
__device__ __align__(256) __half g_w2t[(size_t)NEXP * CDIM * HDIM];
__device__ __align__(256) __half g_h[(size_t)NEXP * NTOK * HDIM];

// ---------------------------------------------------------------------------
// PTX helpers (generic sm_80+ features only — no tcgen05 on this PTX target)
// ---------------------------------------------------------------------------
__device__ __forceinline__ uint32_t smem_u32(const void* p) {
    uint32_t a;
    asm("{ .reg .u64 t; cvta.to.shared.u64 t, %1; cvt.u32.u64 %0, t; }"
        : "=r"(a) : "l"(p));
    return a;
}
__device__ __forceinline__ void cpa16(uint32_t dst, const void* src) {
    asm volatile("cp.async.cg.shared.global [%0], [%1], 16;"
                 :: "r"(dst), "l"(src) : "memory");
}
__device__ __forceinline__ void cpa_commit() {
    asm volatile("cp.async.commit_group;" ::: "memory");
}
template <int N> __device__ __forceinline__ void cpa_wait() {
    asm volatile("cp.async.wait_group %0;" :: "n"(N) : "memory");
}
__device__ __forceinline__ void ldm_x4(uint32_t* r, uint32_t a) {
    asm volatile("ldmatrix.sync.aligned.m8n8.x4.shared.b16 {%0,%1,%2,%3}, [%4];"
                 : "=r"(r[0]), "=r"(r[1]), "=r"(r[2]), "=r"(r[3]) : "r"(a));
}
__device__ __forceinline__ void mma16816(float* c, const uint32_t* a, const uint32_t* b) {
    asm volatile(
        "mma.sync.aligned.m16n8k16.row.col.f32.f16.f16.f32 "
        "{%0,%1,%2,%3}, {%4,%5,%6,%7}, {%8,%9}, {%0,%1,%2,%3};"
        : "+f"(c[0]), "+f"(c[1]), "+f"(c[2]), "+f"(c[3])
        : "r"(a[0]), "r"(a[1]), "r"(a[2]), "r"(a[3]), "r"(b[0]), "r"(b[1]));
}

// ---------------------------------------------------------------------------
// Zero output + counters
// ---------------------------------------------------------------------------
__global__ void zero_kernel(float* __restrict__ out) {
    size_t i = (size_t)blockIdx.x * blockDim.x + threadIdx.x;
    if (i < (size_t)NTOK * CDIM) out[i] = 0.0f;
    if (i < NEXP) g_count[i] = 0;
}

// ---------------------------------------------------------------------------
// Gating: one warp per token
// ---------------------------------------------------------------------------
__global__ void gate_kernel(const float* __restrict__ x,
                            const float* __restrict__ gw) {
    int gtid = blockIdx.x * blockDim.x + threadIdx.x;
    int tok  = gtid >> 5;
    int lane = threadIdx.x & 31;
    if (tok >= NTOK) return;

    float p[NEXP];
#pragma unroll
    for (int e = 0; e < NEXP; e++) p[e] = 0.0f;
    const float* xr = x + (size_t)tok * CDIM;
    for (int k = lane; k < CDIM; k += 32) {
        float xv = xr[k];
        const float* gr = gw + (size_t)k * NEXP;
#pragma unroll
        for (int e = 0; e < NEXP; e++) p[e] += xv * gr[e];
    }
#pragma unroll
    for (int off = 16; off > 0; off >>= 1)
#pragma unroll
        for (int e = 0; e < NEXP; e++)
            p[e] += __shfl_xor_sync(0xFFFFFFFFu, p[e], off);
    if (lane == 0) {
        int e0 = 0;
#pragma unroll
        for (int e = 1; e < NEXP; e++) if (p[e] > p[e0]) e0 = e;
        int e1 = -1;
#pragma unroll
        for (int e = 0; e < NEXP; e++)
            if (e != e0 && (e1 < 0 || p[e] > p[e1])) e1 = e;
        float w0 = 1.0f / (1.0f + expf(p[e1] - p[e0]));
        float w1 = 1.0f - w0;
        int s0 = atomicAdd(&g_count[e0], 1);
        g_bucket[e0][s0] = tok; g_wt[e0][s0] = w0;
        int s1 = atomicAdd(&g_count[e1], 1);
        g_bucket[e1][s1] = tok; g_wt[e1][s1] = w1;
    }
}

// ---------------------------------------------------------------------------
// Gather + convert x rows into per-expert fp16 planes
// ---------------------------------------------------------------------------
__global__ void convert_x_kernel(const float* __restrict__ x) {
    const int e = blockIdx.y, slot = blockIdx.x;
    if (slot >= g_count[e]) return;
    const int tok = g_bucket[e][slot];
    const float4* src = reinterpret_cast<const float4*>(x + (size_t)tok * CDIM);
    __half2* dst = reinterpret_cast<__half2*>(g_xg + ((size_t)e * NTOK + slot) * CDIM);
    for (int i = threadIdx.x; i < CDIM / 4; i += blockDim.x) {
        float4 v = src[i];
        dst[2 * i]     = __floats2half2_rn(v.x, v.y);
        dst[2 * i + 1] = __floats2half2_rn(v.z, v.w);
    }
}

// ---------------------------------------------------------------------------
// Transpose + convert weights: in [e][KD][ND] fp32 -> out [e][ND][KD] fp16
// ---------------------------------------------------------------------------
template <int KD, int ND, bool W1>
__global__ __launch_bounds__(256) void convert_w_kernel(const float* __restrict__ w) {
    __shared__ float tile[32][33];
    const int e = blockIdx.z;
    const float* we = w + (size_t)e * KD * ND;
    const int n0 = blockIdx.x * 32, k0 = blockIdx.y * 32;
    const int tx = threadIdx.x & 31, ty = threadIdx.x >> 5;  // ty 0..7
#pragma unroll
    for (int i = 0; i < 32; i += 8)
        tile[ty + i][tx] = we[(size_t)(k0 + ty + i) * ND + n0 + tx];
    __syncthreads();
    __half* wt = W1 ? g_w1t : g_w2t;
    const int px = threadIdx.x & 15, py = threadIdx.x >> 4;  // py 0..15
#pragma unroll
    for (int g = 0; g < 2; g++) {
        int r = py + g * 16;  // n-local
        float a = tile[2 * px][r], b = tile[2 * px + 1][r];
        size_t o = ((size_t)e * ND + n0 + r) * KD + k0 + 2 * px;
        *reinterpret_cast<__half2*>(wt + o) = __floats2half2_rn(a, b);
    }
}

// ---------------------------------------------------------------------------
// Pipelined fp16 mma.sync GEMM.
// CTA tile 128x256, BK=32, 4 stages (24KB/stage, 96KB). 8 warps, each 64x64.
// Per kh (k16): 4x ldm_x4 (A) + 4x ldm_x4 (B, 2 n-groups each) -> 32 HMMA.
// fp32 accumulate. 64B smem rows, 4 chunks of 16B:
//   phys_chunk = c ^ ((row>>1)&3)   (conflict-free stores + ldmatrix)
// ---------------------------------------------------------------------------
#define GSTAGES 4
#define STAGE_B 24576
#define GSMEM   (GSTAGES * STAGE_B)

template <int KTOT, int NDIM, bool G1>
__global__ __launch_bounds__(256, 1) void moe_gemm_kernel(
    const float* __restrict__ bias, float* __restrict__ outp) {
    const int e = blockIdx.z, mt = blockIdx.y, jt = blockIdx.x;
    const int T = g_count[e];
    if (mt * 128 >= T) return;

    extern __shared__ __align__(1024) char smem[];
    const uint32_t sm = smem_u32(smem);
    const int tid = threadIdx.x, wid = tid >> 5, lane = tid & 31;
    const int warp_m = wid >> 2, warp_n = wid & 3;  // 2 x 4 warps (64m x 64n)

    constexpr int NC = KTOT / 32;

    const __half* aBase =
        (G1 ? g_xg : g_h) + ((size_t)e * NTOK + mt * 128) * KTOT;
    const __half* bBase =
        (G1 ? g_w1t : g_w2t) + ((size_t)e * NDIM + jt * 256) * KTOT;

    float acc[4][8][4];
#pragma unroll
    for (int mi = 0; mi < 4; mi++)
#pragma unroll
        for (int ni = 0; ni < 8; ni++)
#pragma unroll
            for (int r = 0; r < 4; r++) acc[mi][ni][r] = 0.0f;

    // stage: A 128x32 (8KB) at +0, B 256x32 (16KB) at +8192
    auto load_chunk = [&](int kc, int stg) {
        const int kk = kc * 32;
        const __half* asrc = aBase + kk;
        const __half* bsrc = bBase + kk;
        const uint32_t abase = sm + stg * STAGE_B;
        const uint32_t bbase = abase + 8192;
#pragma unroll
        for (int i = 0; i < 2; i++) {   // A: 512 x 16B units
            int u = tid + i * 256;
            int row = u >> 2, c = u & 3;
            int pc = c ^ ((row >> 1) & 3);
            cpa16(abase + row * 64 + pc * 16, asrc + (size_t)row * KTOT + c * 8);
        }
#pragma unroll
        for (int i = 0; i < 4; i++) {   // B: 1024 x 16B units
            int u = tid + i * 256;
            int row = u >> 2, c = u & 3;
            int pc = c ^ ((row >> 1) & 3);
            cpa16(bbase + row * 64 + pc * 16, bsrc + (size_t)row * KTOT + c * 8);
        }
    };

    // register fragments for k-half kh (0..1) of stage stg
    auto frag_load = [&](int stg, int kh, uint32_t a[4][4], uint32_t b[8][2]) {
        const uint32_t sA = sm + stg * STAGE_B;
        const uint32_t sB = sA + 8192;
#pragma unroll
        for (int mi = 0; mi < 4; mi++) {
            int row = warp_m * 64 + mi * 16 + (lane & 15);
            int c = kh * 2 + (lane >> 4);
            int pc = c ^ ((row >> 1) & 3);
            ldm_x4(a[mi], sA + row * 64 + pc * 16);
        }
#pragma unroll
        for (int p = 0; p < 4; p++) {   // each x4: 2 n-groups x 2 k-halves
            int row = warp_n * 64 + p * 16 + ((lane >> 4) & 1) * 8 + (lane & 7);
            int c = kh * 2 + ((lane >> 3) & 1);
            int pc = c ^ ((row >> 1) & 3);
            uint32_t t[4];
            ldm_x4(t, sB + row * 64 + pc * 16);
            b[p * 2][0] = t[0]; b[p * 2][1] = t[1];
            b[p * 2 + 1][0] = t[2]; b[p * 2 + 1][1] = t[3];
        }
    };

    uint32_t af[2][4][4], bf[2][8][2];

    // prologue: prefetch chunks 0..2
#pragma unroll
    for (int s = 0; s < GSTAGES - 1; s++) {
        if (s < NC) load_chunk(s, s);
        cpa_commit();
    }

    for (int kc = 0; kc < NC; kc++) {
        cpa_wait<GSTAGES - 2>();
        __syncthreads();
        const int nx = kc + GSTAGES - 1;
        if (nx < NC) load_chunk(nx, nx & (GSTAGES - 1));
        cpa_commit();
        const int stg = kc & (GSTAGES - 1);
        frag_load(stg, 0, af[0], bf[0]);
#pragma unroll
        for (int kh = 0; kh < 2; kh++) {
            if (kh == 0) frag_load(stg, 1, af[1], bf[1]);
            uint32_t (*a)[4] = af[kh];
            uint32_t (*b)[2] = bf[kh];
#pragma unroll
            for (int mi = 0; mi < 4; mi++)
#pragma unroll
                for (int ni = 0; ni < 8; ni++)
                    mma16816(acc[mi][ni], a[mi], b[ni]);
        }
    }

    // ----- epilogue -----
#pragma unroll
    for (int mi = 0; mi < 4; mi++) {
        const int m0 = mt * 128 + warp_m * 64 + mi * 16 + (lane >> 2);
#pragma unroll
        for (int half = 0; half < 2; half++) {
            const int m = m0 + half * 8;
            if (m >= T) continue;
            if (G1) {
                const size_t hrow = ((size_t)e * NTOK + m) * HDIM;
#pragma unroll
                for (int ni = 0; ni < 8; ni++) {
                    int n = jt * 256 + warp_n * 64 + ni * 8 + (lane & 3) * 2;
                    float v0 = acc[mi][ni][half * 2 + 0] + bias[e * NDIM + n];
                    float v1 = acc[mi][ni][half * 2 + 1] + bias[e * NDIM + n + 1];
                    float g0 = 0.5f * v0 * (1.0f + erff(v0 * 0.70710678118654752f));
                    float g1 = 0.5f * v1 * (1.0f + erff(v1 * 0.70710678118654752f));
                    *reinterpret_cast<__half2*>(g_h + hrow + n) =
                        __floats2half2_rn(g0, g1);
                }
            } else {
                const int tokn = g_bucket[e][m];
                const float wc = g_wt[e][m];
                float* orow = outp + (size_t)tokn * CDIM;
#pragma unroll
                for (int ni = 0; ni < 8; ni++) {
                    int n = jt * 256 + warp_n * 64 + ni * 8 + (lane & 3) * 2;
                    float v0 = acc[mi][ni][half * 2 + 0] + bias[e * NDIM + n];
                    float v1 = acc[mi][ni][half * 2 + 1] + bias[e * NDIM + n + 1];
                    atomicAdd(orow + n, wc * v0);
                    atomicAdd(orow + n + 1, wc * v1);
                }
            }
        }
    }
}

// ---------------------------------------------------------------------------
// Launch
// ---------------------------------------------------------------------------
extern "C" void kernel_launch(void* const* d_in, const int* in_sizes, int n_in,
                              void* d_out, int out_size) {
    const float* x  = (const float*)d_in[0];
    const float* gw = (const float*)d_in[1];
    const float* w1 = (const float*)d_in[2];
    const float* b1 = (const float*)d_in[3];
    const float* w2 = (const float*)d_in[4];
    const float* b2 = (const float*)d_in[5];
    float* out = (float*)d_out;

    cudaFuncSetAttribute((const void*)moe_gemm_kernel<CDIM, HDIM, true>,
                         cudaFuncAttributeMaxDynamicSharedMemorySize, GSMEM);
    cudaFuncSetAttribute((const void*)moe_gemm_kernel<HDIM, CDIM, false>,
                         cudaFuncAttributeMaxDynamicSharedMemorySize, GSMEM);

    zero_kernel<<<(NTOK * CDIM + 255) / 256, 256>>>(out);
    gate_kernel<<<NTOK / 4, 128>>>(x, gw);
    convert_x_kernel<<<dim3(NTOK, NEXP), 128>>>(x);
    convert_w_kernel<CDIM, HDIM, true><<<dim3(HDIM / 32, CDIM / 32, NEXP), 256>>>(w1);
    convert_w_kernel<HDIM, CDIM, false><<<dim3(CDIM / 32, HDIM / 32, NEXP), 256>>>(w2);

    moe_gemm_kernel<CDIM, HDIM, true>
        <<<dim3(HDIM / 256, NTOK / 128, NEXP), 256, GSMEM>>>(b1, nullptr);
    moe_gemm_kernel<HDIM, CDIM, false>
        <<<dim3(CDIM / 256, NTOK / 128, NEXP), 256, GSMEM>>>(b2, out);
}